// round 13
// baseline (speedup 1.0000x reference)
#include <cuda_runtime.h>
#include <cuda_bf16.h>

// Chamfer loss (nearest-target-vertex): B=4, N=16384, M=4096, D=3.
// d2[b,n] = p2 + 2 * min_m (0.5*|v|^2 - p.v);  loss[b] = sum_n d2[b,n] / N
//
// Two-pass, M-split x8. Same per-warp profile as the 43.5us champion but
// 128-thread blocks (2048 of them, 13.8/SM) to halve last-wave imbalance:
//   pass 1: 2048 blocks, 128 thr, 2 pts/thr, 512 targets/block, packed
//           f32x2 FMA dots; stores PRE-BIASED partial (min score + 0.5*p2).
//   pass 2: 256 blocks, 1 pt/thread, fold 8 partials, clamp, reduce.

#define B_ 4
#define N_ 16384
#define M_ 4096
#define SPLITS 8
#define M_PER (M_ / SPLITS)            // 512 targets per block
#define PAIRS_PER (M_PER / 2)          // 256 target pairs
#define THREADS 128
#define PPT 2
#define PTS_PER_BLOCK (THREADS * PPT)            // 256
#define CHUNKS (N_ / PTS_PER_BLOCK)              // 64
#define GRID1 (B_ * CHUNKS * SPLITS)             // 2048
#define SMEM_BYTES (M_PER * 16)                  // 8 KB

typedef unsigned long long u64;

__device__ float g_partial[SPLITS][B_ * N_];     // 2 MB scratch (biased min)

__device__ __forceinline__ u64 pack2(float lo, float hi) {
    u64 r;
    asm("mov.b64 %0, {%1, %2};" : "=l"(r) : "f"(lo), "f"(hi));
    return r;
}
__device__ __forceinline__ void unpack2(u64 v, float& lo, float& hi) {
    asm("mov.b64 {%0, %1}, %2;" : "=f"(lo), "=f"(hi) : "l"(v));
}
__device__ __forceinline__ u64 fma2(u64 a, u64 b, u64 c) {
    u64 d;
    asm("fma.rn.f32x2 %0, %1, %2, %3;" : "=l"(d) : "l"(a), "l"(b), "l"(c));
    return d;
}

__global__ __launch_bounds__(THREADS)
void chamfer_pass1(const float* __restrict__ src,
                   const float* __restrict__ tgt,
                   float* __restrict__ out) {
    extern __shared__ float sv[];   // 256 pairs x 32B (f32x2-ready layout)

    if (blockIdx.x == 0 && threadIdx.x < B_) out[threadIdx.x] = 0.0f;

    const int s     = blockIdx.x % SPLITS;
    const int t     = blockIdx.x / SPLITS;
    const int b     = t / CHUNKS;
    const int chunk = t % CHUNKS;

    // Load this block's 512-target tile (w = 0.5*|v|^2), pair layout:
    //   [ vx0,vx1, vy0,vy1 | vz0,vz1, w0,w1 ] per 32B pair.
    const float* tb = tgt + (size_t)b * M_ * 3 + (size_t)s * M_PER * 3;
    for (int i = threadIdx.x; i < M_PER; i += THREADS) {
        float x = tb[3 * i + 0];
        float y = tb[3 * i + 1];
        float z = tb[3 * i + 2];
        float w = 0.5f * (x * x + y * y + z * z);
        int base = (i >> 1) * 8 + (i & 1);
        sv[base + 0] = x;
        sv[base + 2] = y;
        sv[base + 4] = z;
        sv[base + 6] = w;
    }
    __syncthreads();

    // Per-thread source points, negated + broadcast into f32x2 regs.
    const int pbase = b * N_ + chunk * PTS_PER_BLOCK + threadIdx.x;
    u64 npx2[PPT], npy2[PPT], npz2[PPT];
    float hp2[PPT], mn0[PPT], mn1[PPT];
#pragma unroll
    for (int p = 0; p < PPT; p++) {
        int idx = pbase + p * THREADS;
        float x = src[3 * idx + 0];
        float y = src[3 * idx + 1];
        float z = src[3 * idx + 2];
        npx2[p] = pack2(-x, -x);
        npy2[p] = pack2(-y, -y);
        npz2[p] = pack2(-z, -z);
        hp2[p]  = 0.5f * (x * x + y * y + z * z);
        mn0[p]  = 3.4e38f;
        mn1[p]  = 3.4e38f;
    }

    const ulonglong2* s2 = (const ulonglong2*)sv;
    // Per pair-iter per point: 3 FFMA2 (fma pipe) + 2 FMNMX (alu pipe).
#pragma unroll 8
    for (int j = 0; j < PAIRS_PER; j++) {
        ulonglong2 LA = s2[2 * j];       // (vx2, vy2)
        ulonglong2 LB = s2[2 * j + 1];   // (vz2, w2)
#pragma unroll
        for (int p = 0; p < PPT; p++) {
            u64 acc = fma2(LA.x, npx2[p], LB.y);
            acc = fma2(LA.y, npy2[p], acc);
            acc = fma2(LB.x, npz2[p], acc);
            float a0, a1;
            unpack2(acc, a0, a1);
            mn0[p] = fminf(mn0[p], a0);
            mn1[p] = fminf(mn1[p], a1);
        }
    }

    // PRE-BIASED partial: min(score) + 0.5*p2 (per-point constant shift
    // commutes with the min-fold across splits).
#pragma unroll
    for (int p = 0; p < PPT; p++)
        g_partial[s][pbase + p * THREADS] = fminf(mn0[p], mn1[p]) + hp2[p];
}

#define THREADS2 256
#define GRID2 (B_ * N_ / THREADS2)   // 256 blocks, 1 point per thread

__global__ __launch_bounds__(THREADS2)
void chamfer_pass2(float* __restrict__ out) {
    const int i = blockIdx.x * THREADS2 + threadIdx.x;
    const int b = i >> 14;              // N_ = 16384 points per batch

    // Issue all 8 partial loads back-to-back (MLP=8), then tree-fold.
    float v[SPLITS];
#pragma unroll
    for (int s = 0; s < SPLITS; s++)
        v[s] = g_partial[s][i];

    float m01 = fminf(v[0], v[1]);
    float m23 = fminf(v[2], v[3]);
    float m45 = fminf(v[4], v[5]);
    float m67 = fminf(v[6], v[7]);
    float mn  = fminf(fminf(m01, m23), fminf(m45, m67));

    float local = fmaxf(2.0f * mn, 0.0f);   // d2, pre-biased partials

#pragma unroll
    for (int off = 16; off > 0; off >>= 1)
        local += __shfl_down_sync(0xffffffffu, local, off);

    __shared__ float warp_sums[THREADS2 / 32];
    if ((threadIdx.x & 31) == 0) warp_sums[threadIdx.x >> 5] = local;
    __syncthreads();

    if (threadIdx.x == 0) {
        float ssum = 0.0f;
#pragma unroll
        for (int w = 0; w < THREADS2 / 32; w++)
            ssum += warp_sums[w];
        atomicAdd(&out[b], ssum * (1.0f / N_));
    }
}

extern "C" void kernel_launch(void* const* d_in, const int* in_sizes, int n_in,
                              void* d_out, int out_size) {
    const float* src = (const float*)d_in[0];
    const float* tgt = (const float*)d_in[1];
    if (n_in >= 2 && in_sizes[0] == B_ * M_ * 3 && in_sizes[1] == B_ * N_ * 3) {
        const float* t = src; src = tgt; tgt = t;
    }
    float* out = (float*)d_out;

    chamfer_pass1<<<GRID1, THREADS, SMEM_BYTES>>>(src, tgt, out);
    chamfer_pass2<<<GRID2, THREADS2>>>(out);
}